// round 16
// baseline (speedup 1.0000x reference)
#include <cuda_runtime.h>
#include <math.h>

#define NB 8
#define NL 4096
#define NH 8
#define NM 64
#define NCH 512

typedef unsigned long long u64x;

__device__ ulonglong2 g_ts[4096];
__device__ float2 g_F[8 * NB * NM * NCH];
__device__ float2 g_C[NB * NH * 64 * 64];
__device__ float2 g_O[NB * NH * 64 * NM];

static __device__ __forceinline__ u64x fma2(u64x a, u64x b, u64x c) {
    u64x d; asm("fma.rn.f32x2 %0,%1,%2,%3;" : "=l"(d) : "l"(a), "l"(b), "l"(c)); return d;
}
static __device__ __forceinline__ u64x add2(u64x a, u64x b) {
    u64x d; asm("add.rn.f32x2 %0,%1,%2;" : "=l"(d) : "l"(a), "l"(b)); return d;
}
#define NEG1X2 0xBF800000BF800000ULL
#define KK2    0x3F3504F33F3504F3ULL
#define NKK2   0xBF3504F3BF3504F3ULL
static __device__ __forceinline__ u64x sub2(u64x a, u64x b) { return fma2(b, NEG1X2, a); }
static __device__ __forceinline__ u64x neg2(u64x a) { return fma2(a, NEG1X2, 0ULL); }
static __device__ __forceinline__ void unpack2(u64x d, float& lo, float& hi) {
    asm("mov.b64 {%0,%1},%2;" : "=f"(lo), "=f"(hi) : "l"(d));
}
static __device__ __forceinline__ u64x dup2(float v) {
    u64x d; asm("mov.b64 %0,{%1,%1};" : "=l"(d) : "f"(v)); return d;
}
static __device__ __forceinline__ u64x ldg64(const float* p) {
    u64x v; asm("ld.global.nc.u64 %0,[%1];" : "=l"(v) : "l"(p)); return v;
}

__global__ void k0_init() {
    int i = blockIdx.x * 256 + threadIdx.x;
    if (i < 4096) {
        float s, c;
        sincospif((float)i / 2048.0f, &s, &c);
        g_ts[i] = make_ulonglong2(dup2(c), dup2(s));
    }
}

// 8-pt real-input DFT: F0,F4 real; F1..F3 complex (F5..7 = conj)
static __device__ __forceinline__ void dft8(const u64x e[8],
    u64x& F0, u64x& F4, u64x& F1r, u64x& F1i, u64x& F2r, u64x& F2i, u64x& F3r, u64x& F3i)
{
    u64x e04 = add2(e[0], e[4]), d04 = sub2(e[0], e[4]);
    u64x e26 = add2(e[2], e[6]), d62 = sub2(e[6], e[2]);
    u64x e15 = add2(e[1], e[5]), s1 = sub2(e[1], e[5]);
    u64x e37 = add2(e[3], e[7]), s2 = sub2(e[3], e[7]);
    u64x t1 = sub2(s1, s2), t2 = add2(s1, s2);
    u64x S = add2(e04, e26), T = add2(e15, e37);
    F0 = add2(S, T); F4 = sub2(S, T);
    F2r = sub2(e04, e26); F2i = sub2(e37, e15);
    F1r = fma2(t1, KK2, d04);  F1i = fma2(t2, NKK2, d62);
    F3r = fma2(t1, NKK2, d04); F3i = neg2(fma2(t2, KK2, d62));
}

// ================= K1: forward sparse DFT, radix-16 staged butterfly =================
#define K1_SMEM (4096 * 16 + 16 * 4 * 128 * 4 + 64)
__global__ void __launch_bounds__(256, 2) k1_forward(const float* __restrict__ qp,
                                                     const float* __restrict__ kp,
                                                     const int* __restrict__ iq,
                                                     const int* __restrict__ ikv) {
    extern __shared__ char sm[];
    ulonglong2* ts2 = (ulonglong2*)sm;
    float* xs = (float*)(ts2 + 4096);            // [16 slot][4 t'][128 ch]
    u64x* xsw = (u64x*)xs;
    const ulonglong2* xs2 = (const ulonglong2*)xs;

    const int ctile = blockIdx.x, b = blockIdx.y;
    const int tensor = blockIdx.z >> 2, tq = blockIdx.z & 3;
    const float* src = tensor ? kp : qp;
    const int* idxarr = tensor ? ikv : iq;
    const int tid = threadIdx.x, lane = tid & 31, warp = tid >> 5;
    const unsigned FULL = 0xffffffffu;

    for (int i = tid; i < 4096; i += 256) ts2[i] = g_ts[i];

    const u64x C8 = dup2(0.92387953251128674f);
    const u64x S8 = dup2(0.38268343236508977f);

    int Flo = idxarr[lane], Fhi = idxarr[lane + 32];
    int jlo = Flo & 15, jhi = Fhi & 15;
    int plo = (jlo == 0 || jlo == 8) ? 0 : ((jlo < 16 - jlo) ? jlo : 16 - jlo);
    int phi = (jhi == 0 || jhi == 8) ? 0 : ((jhi < 16 - jhi) ? jhi : 16 - jhi);
    int keylo = plo * 2 + (jlo >= 8);
    int keyhi = phi * 2 + (jhi >= 8);
    unsigned lm = (1u << lane) - 1u;
    int p_lo = 0, p_hi = 0, run = 0;
#pragma unroll
    for (int c = 0; c < 16; c++) {
        unsigned blo = __ballot_sync(FULL, keylo == c);
        unsigned bhi = __ballot_sync(FULL, keyhi == c);
        if (keylo == c) p_lo = run + __popc(blo & lm);
        if (keyhi == c) p_hi = run + __popc(blo) + __popc(bhi & lm);
        run += __popc(blo) + __popc(bhi);
    }
    int F[8], mi[8];
#pragma unroll
    for (int k = 0; k < 8; k++) {
        int tpos = warp * 8 + k;
        unsigned ba = __ballot_sync(FULL, p_lo == tpos);
        unsigned bb = __ballot_sync(FULL, p_hi == tpos);
        int m = ba ? (__ffs(ba) - 1) : (32 + __ffs(bb) - 1);
        mi[k] = m;
        F[k] = __shfl_sync(FULL, (m < 32) ? Flo : Fhi, m & 31);
    }
    bool uni = true;
#pragma unroll
    for (int k = 0; k < 8; k++) {
        int jexp = (k < 4) ? ((warp == 0) ? 0 : warp) : ((warp == 0) ? 8 : 16 - warp);
        uni = uni && ((F[k] & 15) == jexp);
    }

    u64x accR[16], accS[16]; int idx[8];
#pragma unroll
    for (int k = 0; k < 16; k++) { accR[k] = 0; accS[k] = 0; }

    const float* base = src + (size_t)b * NL * NCH + ctile * 128;
    const int stt = tid >> 6, sduo = tid & 63;

    for (int cc = 0; cc < 16; cc++) {
        const int tp0 = tq * 64 + cc * 4;
        __syncthreads();
        {
            const float* gp = base + (size_t)(tp0 + stt) * NCH + sduo * 2;
            u64x a[16];
#pragma unroll
            for (int m = 0; m < 16; m++) a[m] = ldg64(gp + (size_t)m * 256 * NCH);
            u64x ev[8], od[8];
#pragma unroll
            for (int r = 0; r < 8; r++) { ev[r] = a[2 * r]; od[r] = a[2 * r + 1]; }
            u64x E0, E4, E1r, E1i, E2r, E2i, E3r, E3i;
            u64x O0, O4, O1r, O1i, O2r, O2i, O3r, O3i;
            dft8(ev, E0, E4, E1r, E1i, E2r, E2i, E3r, E3i);
            dft8(od, O0, O4, O1r, O1i, O2r, O2i, O3r, O3i);
            u64x o[16];
            o[0] = add2(E0, O0);
            o[1] = sub2(E0, O0);
            o[2] = fma2(O1r, C8, fma2(O1i, S8, E1r));
            o[3] = fma2(O1i, C8, fma2(neg2(O1r), S8, E1i));
            o[4] = fma2(add2(O2r, O2i), KK2, E2r);
            o[5] = fma2(sub2(O2i, O2r), KK2, E2i);
            o[6] = fma2(O3r, S8, fma2(O3i, C8, E3r));
            o[7] = fma2(O3i, S8, fma2(neg2(O3r), C8, E3i));
            o[8] = E4;
            o[9] = neg2(O4);
            o[10] = sub2(add2(E3r, E3r), o[6]);  o[11] = sub2(o[7], add2(E3i, E3i));
            o[12] = sub2(add2(E2r, E2r), o[4]);  o[13] = sub2(o[5], add2(E2i, E2i));
            o[14] = sub2(add2(E1r, E1r), o[2]);  o[15] = sub2(o[3], add2(E1i, E1i));
#pragma unroll
            for (int s = 0; s < 16; s++) xsw[(s * 4 + stt) * 64 + sduo] = o[s];
        }
        __syncthreads();
#pragma unroll
        for (int k = 0; k < 8; k++) idx[k] = (F[k] * tp0) & 4095;

        if (uni && warp > 0) {
            const int pRE = 2 * warp, pIM = 2 * warp + 1;
#pragma unroll
            for (int tt = 0; tt < 4; tt++) {
                ulonglong2 RE = xs2[(pRE * 4 + tt) * 32 + lane];
                ulonglong2 IM = xs2[(pIM * 4 + tt) * 32 + lane];
                u64x nIMx = neg2(IM.x), nIMy = neg2(IM.y);
#pragma unroll
                for (int k = 0; k < 8; k++) {
                    ulonglong2 cs = ts2[idx[k]];
                    u64x pix = (k < 4) ? IM.x : nIMx, npix = (k < 4) ? nIMx : IM.x;
                    u64x piy = (k < 4) ? IM.y : nIMy, npiy = (k < 4) ? nIMy : IM.y;
                    accR[k * 2 + 0] = fma2(RE.x, cs.x, accR[k * 2 + 0]);
                    accR[k * 2 + 0] = fma2(pix,  cs.y, accR[k * 2 + 0]);
                    accS[k * 2 + 0] = fma2(RE.x, cs.y, accS[k * 2 + 0]);
                    accS[k * 2 + 0] = fma2(npix, cs.x, accS[k * 2 + 0]);
                    accR[k * 2 + 1] = fma2(RE.y, cs.x, accR[k * 2 + 1]);
                    accR[k * 2 + 1] = fma2(piy,  cs.y, accR[k * 2 + 1]);
                    accS[k * 2 + 1] = fma2(RE.y, cs.y, accS[k * 2 + 1]);
                    accS[k * 2 + 1] = fma2(npiy, cs.x, accS[k * 2 + 1]);
                    idx[k] = (idx[k] + F[k]) & 4095;
                }
            }
        } else if (uni) {
#pragma unroll
            for (int tt = 0; tt < 4; tt++) {
                ulonglong2 R0 = xs2[(0 * 4 + tt) * 32 + lane];
                ulonglong2 R8 = xs2[(1 * 4 + tt) * 32 + lane];
#pragma unroll
                for (int k = 0; k < 8; k++) {
                    ulonglong2 cs = ts2[idx[k]];
                    u64x prx = (k < 4) ? R0.x : R8.x;
                    u64x pry = (k < 4) ? R0.y : R8.y;
                    accR[k * 2 + 0] = fma2(prx, cs.x, accR[k * 2 + 0]);
                    accS[k * 2 + 0] = fma2(prx, cs.y, accS[k * 2 + 0]);
                    accR[k * 2 + 1] = fma2(pry, cs.x, accR[k * 2 + 1]);
                    accS[k * 2 + 1] = fma2(pry, cs.y, accS[k * 2 + 1]);
                    idx[k] = (idx[k] + F[k]) & 4095;
                }
            }
        } else {
            for (int tt = 0; tt < 4; tt++) {
#pragma unroll
                for (int k = 0; k < 8; k++) {
                    int j = F[k] & 15;
                    int jj = (j > 8) ? (16 - j) : j;
                    bool realu = (j == 0) || (j == 8);
                    int sR = (j == 0) ? 0 : ((j == 8) ? 1 : 2 * jj);
                    ulonglong2 RE = xs2[(sR * 4 + tt) * 32 + lane];
                    u64x pix = 0, piy = 0;
                    if (!realu) {
                        ulonglong2 IM = xs2[((2 * jj + 1) * 4 + tt) * 32 + lane];
                        pix = (j > 8) ? neg2(IM.x) : IM.x;
                        piy = (j > 8) ? neg2(IM.y) : IM.y;
                    }
                    ulonglong2 cs = ts2[idx[k]];
                    accR[k * 2 + 0] = fma2(RE.x, cs.x, accR[k * 2 + 0]);
                    accR[k * 2 + 0] = fma2(pix,  cs.y, accR[k * 2 + 0]);
                    accS[k * 2 + 0] = fma2(RE.x, cs.y, accS[k * 2 + 0]);
                    accS[k * 2 + 0] = fma2(neg2(pix), cs.x, accS[k * 2 + 0]);
                    accR[k * 2 + 1] = fma2(RE.y, cs.x, accR[k * 2 + 1]);
                    accR[k * 2 + 1] = fma2(piy,  cs.y, accR[k * 2 + 1]);
                    accS[k * 2 + 1] = fma2(RE.y, cs.y, accS[k * 2 + 1]);
                    accS[k * 2 + 1] = fma2(neg2(piy), cs.x, accS[k * 2 + 1]);
                    idx[k] = (idx[k] + F[k]) & 4095;
                }
            }
        }
    }

    const int ch = ctile * 128 + lane * 4;
    float2* dst = g_F + ((size_t)((tq * 2 + tensor) * NB + b) * NM) * NCH;
#pragma unroll
    for (int k = 0; k < 8; k++) {
        float r0, r1, r2, r3, s0, s1, s2, s3;
        unpack2(accR[k * 2 + 0], r0, r1);
        unpack2(accS[k * 2 + 0], s0, s1);
        unpack2(accR[k * 2 + 1], r2, r3);
        unpack2(accS[k * 2 + 1], s2, s3);
        float2* dp = &dst[(size_t)mi[k] * NCH + ch];
        *(float4*)(dp)     = make_float4(r0, -s0, r1, -s1);
        *(float4*)(dp + 2) = make_float4(r2, -s2, r3, -s3);
    }
}

// ================= K2a =================
#define K2A_SMEM (32 * 64 * 8 + 64 * 65 * 8 + 64 * 33 * 8)
__global__ void __launch_bounds__(256, 3) k2a_attn() {
    extern __shared__ char sm[];
    float2* sFq  = (float2*)sm;
    float2* sFkT = sFq + 32 * 64;
    float2* sA   = sFkT + 64 * 65;

    const int bh = blockIdx.x, b = bh >> 3, h = bh & 7;
    const int x0 = blockIdx.y * 32;
    const int tid = threadIdx.x;
    const size_t QSTR = (size_t)2 * NB * NM * NCH;

    for (int i = tid; i < 2048; i += 256) {
        int xl = i >> 6, e = i & 63;
        size_t o0 = ((size_t)(b) * NM + (x0 + xl)) * NCH + h * 64 + e;
        float2 a0 = g_F[o0], a1 = g_F[o0 + QSTR], a2 = g_F[o0 + 2 * QSTR], a3 = g_F[o0 + 3 * QSTR];
        sFq[xl * 64 + e] = make_float2(a0.x + a1.x + a2.x + a3.x, a0.y + a1.y + a2.y + a3.y);
    }
    for (int i = tid; i < 4096; i += 256) {
        int e = i & 63, f = i >> 6;
        size_t o0 = ((size_t)(NB + b) * NM + f) * NCH + h * 64 + e;
        float2 a0 = g_F[o0], a1 = g_F[o0 + QSTR], a2 = g_F[o0 + 2 * QSTR], a3 = g_F[o0 + 3 * QSTR];
        sFkT[e * 65 + f] = make_float2(a0.x + a1.x + a2.x + a3.x, a0.y + a1.y + a2.y + a3.y);
    }
    __syncthreads();

#pragma unroll 1
    for (int p = 0; p < 8; p++) {
        int i = p * 256 + tid, xl = i >> 6, y = i & 63;
        float re = 0.f, im = 0.f;
#pragma unroll 4
        for (int e = 0; e < 64; e++) {
            float2 a = sFq[xl * 64 + e];
            float2 c = sFkT[e * 65 + y];
            re += a.x * c.x - a.y * c.y;
            im += a.x * c.y + a.y * c.x;
        }
        sA[y * 33 + xl] = make_float2(tanhf(re), tanhf(im));
    }
    __syncthreads();

#pragma unroll 1
    for (int p = 0; p < 8; p++) {
        int i = p * 256 + tid, xl = i & 31, e = i >> 5;
        float re = 0.f, im = 0.f;
#pragma unroll 4
        for (int y = 0; y < 64; y++) {
            float2 a  = sA[y * 33 + xl];
            float2 kv = sFkT[e * 65 + y];
            re += a.x * kv.x - a.y * kv.y;
            im += a.x * kv.y + a.y * kv.x;
        }
        g_C[((size_t)(h * 8 + b) * 64 + e) * 64 + x0 + xl] = make_float2(re, im);
    }
}

// ================= K2b: weight contraction, float4 w loads (4x MLP) =================
// thread (o = tid&63, bq = tid>>6): owns all 4 x of the tile, 2 b values {2bq, 2bq+1}
#define K2B_SMEM (8 * 64 * 4 * 8)
__global__ void __launch_bounds__(256, 4) k2b_wproj(const float* __restrict__ w1,
                                                    const float* __restrict__ w2,
                                                    const int* __restrict__ iq) {
    extern __shared__ char sm[];
    float2* sC = (float2*)sm;                // [8 b][64 e][4 xl]

    const int h = blockIdx.x, x0 = blockIdx.y * 4;
    const int tid = threadIdx.x;

    for (int i = tid; i < 2048; i += 256) {
        int xl = i & 3, e = (i >> 2) & 63, b = i >> 8;
        sC[(b * 64 + e) * 4 + xl] = g_C[((size_t)(h * 8 + b) * 64 + e) * 64 + x0 + xl];
    }
    __syncthreads();

    const int o = tid & 63, bq = tid >> 6;   // b = 2bq, 2bq+1
    float accR[2][4], accI[2][4];
#pragma unroll
    for (int bb = 0; bb < 2; bb++)
#pragma unroll
        for (int xl = 0; xl < 4; xl++) { accR[bb][xl] = 0.f; accI[bb][xl] = 0.f; }

    const float4* w1p = (const float4*)(w1 + (size_t)h * 262144 + (size_t)o * 64 + x0);
    const float4* w2p = (const float4*)(w2 + (size_t)h * 262144 + (size_t)o * 64 + x0);

#pragma unroll 2
    for (int e = 0; e < 64; e++) {
        float4 wr = __ldg(w1p + (size_t)e * 1024);
        float4 wi = __ldg(w2p + (size_t)e * 1024);
#pragma unroll
        for (int bb = 0; bb < 2; bb++) {
            const float2* cp = &sC[((bq * 2 + bb) * 64 + e) * 4];
            float2 c0 = cp[0], c1 = cp[1], c2 = cp[2], c3 = cp[3];   // warp-broadcast
            accR[bb][0] += c0.x * wr.x - c0.y * wi.x;  accI[bb][0] += c0.x * wi.x + c0.y * wr.x;
            accR[bb][1] += c1.x * wr.y - c1.y * wi.y;  accI[bb][1] += c1.x * wi.y + c1.y * wr.y;
            accR[bb][2] += c2.x * wr.z - c2.y * wi.z;  accI[bb][2] += c2.x * wi.z + c2.y * wr.z;
            accR[bb][3] += c3.x * wr.w - c3.y * wi.w;  accI[bb][3] += c3.x * wi.w + c3.y * wr.w;
        }
    }

    float s[4];
#pragma unroll
    for (int xl = 0; xl < 4; xl++) {
        int fx = iq[x0 + xl];
        s[xl] = ((fx == 0) || (fx == NL / 2) ? 1.0f : 2.0f) * 9.313225746154785e-10f; // 2^-30
    }
#pragma unroll
    for (int bb = 0; bb < 2; bb++) {
        int row = ((bq * 2 + bb) * 8 + h) * 64 + o;
        float2* op = &g_O[(size_t)row * NM + x0];
        *(float4*)(op)     = make_float4(s[0] * accR[bb][0], -s[0] * accI[bb][0],
                                         s[1] * accR[bb][1], -s[1] * accI[bb][1]);
        *(float4*)(op + 2) = make_float4(s[2] * accR[bb][2], -s[2] * accI[bb][2],
                                         s[3] * accR[bb][3], -s[3] * accI[bb][3]);
    }
}

// ================= K3: inverse sparse DFT (radix-8, conj-folded) =================
static __device__ __forceinline__ void k3_seg_real(int lo, int hi, const int2* __restrict__ sperm,
    const ulonglong2* __restrict__ sAd, const ulonglong2* __restrict__ sBd,
    const ulonglong2* __restrict__ ts2, int lane, int t0, u64x P[4])
{
#pragma unroll 2
    for (int pos = lo; pos < hi; pos++) {
        int2 pf = sperm[pos];
        ulonglong2 A = sAd[pf.x * 32 + lane], B = sBd[pf.x * 32 + lane];
        int id = (pf.y * t0) & 4095;
#pragma unroll
        for (int j = 0; j < 2; j++) {
            ulonglong2 cs = ts2[id];
            P[j * 2 + 0] = fma2(A.x, cs.x, P[j * 2 + 0]);  P[j * 2 + 0] = fma2(B.x, cs.y, P[j * 2 + 0]);
            P[j * 2 + 1] = fma2(A.y, cs.x, P[j * 2 + 1]);  P[j * 2 + 1] = fma2(B.y, cs.y, P[j * 2 + 1]);
            id = (id + pf.y) & 4095;
        }
    }
}
template<bool FOLD>
static __device__ __forceinline__ void k3_seg_cplx(int lo, int hi, const int2* __restrict__ sperm,
    const ulonglong2* __restrict__ sAd, const ulonglong2* __restrict__ sBd,
    const ulonglong2* __restrict__ ts2, int lane, int t0, u64x Vr[4], u64x Vi[4])
{
#pragma unroll 2
    for (int pos = lo; pos < hi; pos++) {
        int2 pf = sperm[pos];
        ulonglong2 A = sAd[pf.x * 32 + lane], B = sBd[pf.x * 32 + lane];
        u64x nAx = neg2(A.x), nAy = neg2(A.y);
        u64x nBx = neg2(B.x), nBy = neg2(B.y);
        int id = (pf.y * t0) & 4095;
#pragma unroll
        for (int j = 0; j < 2; j++) {
            ulonglong2 cs = ts2[id];
            Vr[j * 2 + 0] = fma2(A.x, cs.x, Vr[j * 2 + 0]);  Vr[j * 2 + 0] = fma2(B.x, cs.y, Vr[j * 2 + 0]);
            Vr[j * 2 + 1] = fma2(A.y, cs.x, Vr[j * 2 + 1]);  Vr[j * 2 + 1] = fma2(B.y, cs.y, Vr[j * 2 + 1]);
            if (!FOLD) {
                Vi[j * 2 + 0] = fma2(A.x, cs.y, Vi[j * 2 + 0]);  Vi[j * 2 + 0] = fma2(nBx, cs.x, Vi[j * 2 + 0]);
                Vi[j * 2 + 1] = fma2(A.y, cs.y, Vi[j * 2 + 1]);  Vi[j * 2 + 1] = fma2(nBy, cs.x, Vi[j * 2 + 1]);
            } else {
                Vi[j * 2 + 0] = fma2(B.x, cs.x, Vi[j * 2 + 0]);  Vi[j * 2 + 0] = fma2(nAx, cs.y, Vi[j * 2 + 0]);
                Vi[j * 2 + 1] = fma2(B.y, cs.x, Vi[j * 2 + 1]);  Vi[j * 2 + 1] = fma2(nAy, cs.y, Vi[j * 2 + 1]);
            }
            id = (id + pf.y) & 4095;
        }
    }
}

#define K3_SMEM (4096 * 16 + 32768 + 32768 + 128 * 33 * 4 + 64 * 8 + 64)
__global__ void __launch_bounds__(512, 1) k3_inverse(float* __restrict__ out,
                                                     const int* __restrict__ iq) {
    extern __shared__ char sm[];
    ulonglong2* ts2 = (ulonglong2*)sm;
    float* sA = (float*)(ts2 + 4096);
    float* sB = sA + 64 * 128;
    float* sT = sB + 64 * 128;                    // [128 rows][33]
    int2* sperm = (int2*)(sT + 128 * 33);
    int* soff = (int*)(sperm + 64);

    const int rt = blockIdx.x;
    const int tq = blockIdx.y;
    const int r0 = rt * 128;
    const int tid = threadIdx.x, lane = tid & 31, warp = tid >> 5;

    for (int i = tid; i < 4096; i += 512) ts2[i] = g_ts[i];
    for (int i = tid; i < 8192; i += 512) {
        int rr = i >> 6, f = i & 63;
        float2 v = g_O[(size_t)(r0 + rr) * NM + f];
        int half = rr >> 6, pr = (rr & 63) >> 1, sl = half * 2 + (rr & 1);
        sA[f * 128 + pr * 4 + sl] = v.x;
        sB[f * 128 + pr * 4 + sl] = v.y;
    }
    if (warp == 0) {
        const unsigned FULL = 0xffffffffu;
        int Flo = iq[lane], Fhi = iq[lane + 32];
        int clo = Flo & 7, chi = Fhi & 7;
        unsigned mlo[8], mhi[8];
        int off[9]; off[0] = 0;
#pragma unroll
        for (int c = 0; c < 8; c++) {
            mlo[c] = __ballot_sync(FULL, clo == c);
            mhi[c] = __ballot_sync(FULL, chi == c);
        }
#pragma unroll
        for (int c = 0; c < 8; c++) off[c + 1] = off[c] + __popc(mlo[c]) + __popc(mhi[c]);
        unsigned lmm = (1u << lane) - 1u;
        int p_lo = off[clo] + __popc(mlo[clo] & lmm);
        int p_hi = off[chi] + __popc(mlo[chi]) + __popc(mhi[chi] & lmm);
        sperm[p_lo] = make_int2(lane, Flo);
        sperm[p_hi] = make_int2(lane + 32, Fhi);
        if (lane < 9) soff[lane] = off[lane];
    }
    __syncthreads();

    const ulonglong2* sAd = (const ulonglong2*)sA;
    const ulonglong2* sBd = (const ulonglong2*)sB;
    int o[9];
#pragma unroll
    for (int c = 0; c < 9; c++) o[c] = soff[c];

#pragma unroll 1
    for (int pass = 0; pass < 4; pass++) {
        const int t0 = tq * 128 + pass * 32 + warp * 2;
        u64x P0[4], P4[4], V1r[4], V1i[4], V2r[4], V2i[4], V3r[4], V3i[4];
#pragma unroll
        for (int j = 0; j < 4; j++) {
            P0[j] = 0; P4[j] = 0; V1r[j] = 0; V1i[j] = 0;
            V2r[j] = 0; V2i[j] = 0; V3r[j] = 0; V3i[j] = 0;
        }

        k3_seg_real(o[0], o[1], sperm, sAd, sBd, ts2, lane, t0, P0);
        k3_seg_cplx<false>(o[1], o[2], sperm, sAd, sBd, ts2, lane, t0, V1r, V1i);
        k3_seg_cplx<false>(o[2], o[3], sperm, sAd, sBd, ts2, lane, t0, V2r, V2i);
        k3_seg_cplx<false>(o[3], o[4], sperm, sAd, sBd, ts2, lane, t0, V3r, V3i);
        k3_seg_real(o[4], o[5], sperm, sAd, sBd, ts2, lane, t0, P4);
        k3_seg_cplx<true>(o[5], o[6], sperm, sAd, sBd, ts2, lane, t0, V3r, V3i);
        k3_seg_cplx<true>(o[6], o[7], sperm, sAd, sBd, ts2, lane, t0, V2r, V2i);
        k3_seg_cplx<true>(o[7], o[8], sperm, sAd, sBd, ts2, lane, t0, V1r, V1i);

#pragma unroll 1
        for (int m = 0; m < 8; m++) {
            __syncthreads();
#pragma unroll
            for (int j = 0; j < 2; j++) {
#pragma unroll
                for (int p = 0; p < 2; p++) {
                    const int q = j * 2 + p;
                    u64x a = add2(P0[q], P4[q]);
                    u64x bb = sub2(P0[q], P4[q]);
                    u64x S;
                    if (m == 0) {
                        S = add2(add2(a, V1r[q]), add2(V2r[q], V3r[q]));
                    } else if (m == 1) {
                        u64x t1 = fma2(sub2(V1r[q], V1i[q]), KK2, bb);
                        u64x u2 = fma2(add2(V3r[q], V3i[q]), NKK2, neg2(V2i[q]));
                        S = add2(t1, u2);
                    } else if (m == 2) {
                        S = add2(sub2(sub2(a, V1i[q]), V2r[q]), V3i[q]);
                    } else if (m == 3) {
                        u64x t2 = fma2(add2(V1r[q], V1i[q]), NKK2, bb);
                        u64x u1 = fma2(sub2(V3r[q], V3i[q]), KK2, V2i[q]);
                        S = add2(t2, u1);
                    } else if (m == 4) {
                        S = sub2(add2(sub2(a, V1r[q]), V2r[q]), V3r[q]);
                    } else if (m == 5) {
                        u64x t1 = fma2(sub2(V1r[q], V1i[q]), NKK2, bb);
                        u64x u2 = fma2(add2(V3r[q], V3i[q]), KK2, neg2(V2i[q]));
                        S = add2(t1, u2);
                    } else if (m == 6) {
                        S = sub2(sub2(add2(a, V1i[q]), V2r[q]), V3i[q]);
                    } else {
                        u64x t2 = fma2(add2(V1r[q], V1i[q]), KK2, bb);
                        u64x u1 = fma2(sub2(V3r[q], V3i[q]), NKK2, V2i[q]);
                        S = add2(t2, u1);
                    }
                    float v0, v1;
                    unpack2(S, v0, v1);
                    int tl = warp * 2 + j;
                    int rbase = p * 64 + 2 * lane;
                    sT[rbase * 33 + tl]       = v0;
                    sT[(rbase + 1) * 33 + tl] = v1;
                }
            }
            __syncthreads();
            int tbase = m * 512 + tq * 128 + pass * 32;
#pragma unroll
            for (int ii = 0; ii < 2; ii++) {
                int i = ii * 512 + tid;
                int rr = i >> 3, c4 = i & 7;
                const float* sp = sT + rr * 33 + c4 * 4;
                float4 vv = make_float4(sp[0], sp[1], sp[2], sp[3]);
                *(float4*)&out[(size_t)(r0 + rr) * NL + tbase + c4 * 4] = vv;
            }
        }
    }
}

// ================= launch =================
extern "C" void kernel_launch(void* const* d_in, const int* in_sizes, int n_in,
                              void* d_out, int out_size) {
    const float* q  = (const float*)d_in[0];
    const float* k  = (const float*)d_in[1];
    const float* w1 = (const float*)d_in[3];
    const float* w2 = (const float*)d_in[4];
    const int* iq   = (const int*)d_in[5];
    const int* ikv  = (const int*)d_in[6];
    float* out = (float*)d_out;

    cudaFuncSetAttribute(k1_forward, cudaFuncAttributeMaxDynamicSharedMemorySize, K1_SMEM);
    cudaFuncSetAttribute(k2a_attn,   cudaFuncAttributeMaxDynamicSharedMemorySize, K2A_SMEM);
    cudaFuncSetAttribute(k2b_wproj,  cudaFuncAttributeMaxDynamicSharedMemorySize, K2B_SMEM);
    cudaFuncSetAttribute(k3_inverse, cudaFuncAttributeMaxDynamicSharedMemorySize, K3_SMEM);

    k0_init<<<16, 256>>>();
    k1_forward<<<dim3(4, NB, 8), 256, K1_SMEM>>>(q, k, iq, ikv);
    k2a_attn<<<dim3(NB * NH, 2), 256, K2A_SMEM>>>();
    k2b_wproj<<<dim3(NH, 16), 256, K2B_SMEM>>>(w1, w2, iq);
    k3_inverse<<<dim3(32, 4), 512, K3_SMEM>>>(out, iq);
}

// round 17
// speedup vs baseline: 1.1063x; 1.1063x over previous
#include <cuda_runtime.h>
#include <math.h>

#define NB 8
#define NL 4096
#define NH 8
#define NM 64
#define NCH 512

typedef unsigned long long u64x;

__device__ ulonglong2 g_ts[4096];
__device__ float2 g_F[8 * NB * NM * NCH];
__device__ float2 g_C[NB * NH * 64 * 64];
__device__ float2 g_O[NB * NH * 64 * NM];

static __device__ __forceinline__ u64x fma2(u64x a, u64x b, u64x c) {
    u64x d; asm("fma.rn.f32x2 %0,%1,%2,%3;" : "=l"(d) : "l"(a), "l"(b), "l"(c)); return d;
}
static __device__ __forceinline__ u64x add2(u64x a, u64x b) {
    u64x d; asm("add.rn.f32x2 %0,%1,%2;" : "=l"(d) : "l"(a), "l"(b)); return d;
}
#define NEG1X2 0xBF800000BF800000ULL
#define KK2    0x3F3504F33F3504F3ULL
#define NKK2   0xBF3504F3BF3504F3ULL
static __device__ __forceinline__ u64x sub2(u64x a, u64x b) { return fma2(b, NEG1X2, a); }
static __device__ __forceinline__ u64x neg2(u64x a) { return fma2(a, NEG1X2, 0ULL); }
static __device__ __forceinline__ void unpack2(u64x d, float& lo, float& hi) {
    asm("mov.b64 {%0,%1},%2;" : "=f"(lo), "=f"(hi) : "l"(d));
}
static __device__ __forceinline__ u64x dup2(float v) {
    u64x d; asm("mov.b64 %0,{%1,%1};" : "=l"(d) : "f"(v)); return d;
}
static __device__ __forceinline__ u64x ldg64(const float* p) {
    u64x v; asm("ld.global.nc.u64 %0,[%1];" : "=l"(v) : "l"(p)); return v;
}

__global__ void k0_init() {
    int i = blockIdx.x * 256 + threadIdx.x;
    if (i < 4096) {
        float s, c;
        sincospif((float)i / 2048.0f, &s, &c);
        g_ts[i] = make_ulonglong2(dup2(c), dup2(s));
    }
}

// 8-pt real-input DFT: F0,F4 real; F1..F3 complex (F5..7 = conj)
static __device__ __forceinline__ void dft8(const u64x e[8],
    u64x& F0, u64x& F4, u64x& F1r, u64x& F1i, u64x& F2r, u64x& F2i, u64x& F3r, u64x& F3i)
{
    u64x e04 = add2(e[0], e[4]), d04 = sub2(e[0], e[4]);
    u64x e26 = add2(e[2], e[6]), d62 = sub2(e[6], e[2]);
    u64x e15 = add2(e[1], e[5]), s1 = sub2(e[1], e[5]);
    u64x e37 = add2(e[3], e[7]), s2 = sub2(e[3], e[7]);
    u64x t1 = sub2(s1, s2), t2 = add2(s1, s2);
    u64x S = add2(e04, e26), T = add2(e15, e37);
    F0 = add2(S, T); F4 = sub2(S, T);
    F2r = sub2(e04, e26); F2i = sub2(e37, e15);
    F1r = fma2(t1, KK2, d04);  F1i = fma2(t2, NKK2, d62);
    F3r = fma2(t1, NKK2, d04); F3i = neg2(fma2(t2, KK2, d62));
}

// ================= K1: forward sparse DFT, radix-16 staged butterfly =================
#define K1_SMEM (4096 * 16 + 16 * 4 * 128 * 4 + 64)
__global__ void __launch_bounds__(256, 2) k1_forward(const float* __restrict__ qp,
                                                     const float* __restrict__ kp,
                                                     const int* __restrict__ iq,
                                                     const int* __restrict__ ikv) {
    extern __shared__ char sm[];
    ulonglong2* ts2 = (ulonglong2*)sm;
    float* xs = (float*)(ts2 + 4096);            // [16 slot][4 t'][128 ch]
    u64x* xsw = (u64x*)xs;
    const ulonglong2* xs2 = (const ulonglong2*)xs;

    const int ctile = blockIdx.x, b = blockIdx.y;
    const int tensor = blockIdx.z >> 2, tq = blockIdx.z & 3;
    const float* src = tensor ? kp : qp;
    const int* idxarr = tensor ? ikv : iq;
    const int tid = threadIdx.x, lane = tid & 31, warp = tid >> 5;
    const unsigned FULL = 0xffffffffu;

    for (int i = tid; i < 4096; i += 256) ts2[i] = g_ts[i];

    const u64x C8 = dup2(0.92387953251128674f);
    const u64x S8 = dup2(0.38268343236508977f);

    int Flo = idxarr[lane], Fhi = idxarr[lane + 32];
    int jlo = Flo & 15, jhi = Fhi & 15;
    int plo = (jlo == 0 || jlo == 8) ? 0 : ((jlo < 16 - jlo) ? jlo : 16 - jlo);
    int phi = (jhi == 0 || jhi == 8) ? 0 : ((jhi < 16 - jhi) ? jhi : 16 - jhi);
    int keylo = plo * 2 + (jlo >= 8);
    int keyhi = phi * 2 + (jhi >= 8);
    unsigned lm = (1u << lane) - 1u;
    int p_lo = 0, p_hi = 0, run = 0;
#pragma unroll
    for (int c = 0; c < 16; c++) {
        unsigned blo = __ballot_sync(FULL, keylo == c);
        unsigned bhi = __ballot_sync(FULL, keyhi == c);
        if (keylo == c) p_lo = run + __popc(blo & lm);
        if (keyhi == c) p_hi = run + __popc(blo) + __popc(bhi & lm);
        run += __popc(blo) + __popc(bhi);
    }
    int F[8], mi[8];
#pragma unroll
    for (int k = 0; k < 8; k++) {
        int tpos = warp * 8 + k;
        unsigned ba = __ballot_sync(FULL, p_lo == tpos);
        unsigned bb = __ballot_sync(FULL, p_hi == tpos);
        int m = ba ? (__ffs(ba) - 1) : (32 + __ffs(bb) - 1);
        mi[k] = m;
        F[k] = __shfl_sync(FULL, (m < 32) ? Flo : Fhi, m & 31);
    }
    bool uni = true;
#pragma unroll
    for (int k = 0; k < 8; k++) {
        int jexp = (k < 4) ? ((warp == 0) ? 0 : warp) : ((warp == 0) ? 8 : 16 - warp);
        uni = uni && ((F[k] & 15) == jexp);
    }

    u64x accR[16], accS[16]; int idx[8];
#pragma unroll
    for (int k = 0; k < 16; k++) { accR[k] = 0; accS[k] = 0; }

    const float* base = src + (size_t)b * NL * NCH + ctile * 128;
    const int stt = tid >> 6, sduo = tid & 63;

    for (int cc = 0; cc < 16; cc++) {
        const int tp0 = tq * 64 + cc * 4;
        __syncthreads();
        {
            const float* gp = base + (size_t)(tp0 + stt) * NCH + sduo * 2;
            u64x a[16];
#pragma unroll
            for (int m = 0; m < 16; m++) a[m] = ldg64(gp + (size_t)m * 256 * NCH);
            u64x ev[8], od[8];
#pragma unroll
            for (int r = 0; r < 8; r++) { ev[r] = a[2 * r]; od[r] = a[2 * r + 1]; }
            u64x E0, E4, E1r, E1i, E2r, E2i, E3r, E3i;
            u64x O0, O4, O1r, O1i, O2r, O2i, O3r, O3i;
            dft8(ev, E0, E4, E1r, E1i, E2r, E2i, E3r, E3i);
            dft8(od, O0, O4, O1r, O1i, O2r, O2i, O3r, O3i);
            u64x o[16];
            o[0] = add2(E0, O0);
            o[1] = sub2(E0, O0);
            o[2] = fma2(O1r, C8, fma2(O1i, S8, E1r));
            o[3] = fma2(O1i, C8, fma2(neg2(O1r), S8, E1i));
            o[4] = fma2(add2(O2r, O2i), KK2, E2r);
            o[5] = fma2(sub2(O2i, O2r), KK2, E2i);
            o[6] = fma2(O3r, S8, fma2(O3i, C8, E3r));
            o[7] = fma2(O3i, S8, fma2(neg2(O3r), C8, E3i));
            o[8] = E4;
            o[9] = neg2(O4);
            o[10] = sub2(add2(E3r, E3r), o[6]);  o[11] = sub2(o[7], add2(E3i, E3i));
            o[12] = sub2(add2(E2r, E2r), o[4]);  o[13] = sub2(o[5], add2(E2i, E2i));
            o[14] = sub2(add2(E1r, E1r), o[2]);  o[15] = sub2(o[3], add2(E1i, E1i));
#pragma unroll
            for (int s = 0; s < 16; s++) xsw[(s * 4 + stt) * 64 + sduo] = o[s];
        }
        __syncthreads();
#pragma unroll
        for (int k = 0; k < 8; k++) idx[k] = (F[k] * tp0) & 4095;

        if (uni && warp > 0) {
            const int pRE = 2 * warp, pIM = 2 * warp + 1;
#pragma unroll
            for (int tt = 0; tt < 4; tt++) {
                ulonglong2 RE = xs2[(pRE * 4 + tt) * 32 + lane];
                ulonglong2 IM = xs2[(pIM * 4 + tt) * 32 + lane];
                u64x nIMx = neg2(IM.x), nIMy = neg2(IM.y);
#pragma unroll
                for (int k = 0; k < 8; k++) {
                    ulonglong2 cs = ts2[idx[k]];
                    u64x pix = (k < 4) ? IM.x : nIMx, npix = (k < 4) ? nIMx : IM.x;
                    u64x piy = (k < 4) ? IM.y : nIMy, npiy = (k < 4) ? nIMy : IM.y;
                    accR[k * 2 + 0] = fma2(RE.x, cs.x, accR[k * 2 + 0]);
                    accR[k * 2 + 0] = fma2(pix,  cs.y, accR[k * 2 + 0]);
                    accS[k * 2 + 0] = fma2(RE.x, cs.y, accS[k * 2 + 0]);
                    accS[k * 2 + 0] = fma2(npix, cs.x, accS[k * 2 + 0]);
                    accR[k * 2 + 1] = fma2(RE.y, cs.x, accR[k * 2 + 1]);
                    accR[k * 2 + 1] = fma2(piy,  cs.y, accR[k * 2 + 1]);
                    accS[k * 2 + 1] = fma2(RE.y, cs.y, accS[k * 2 + 1]);
                    accS[k * 2 + 1] = fma2(npiy, cs.x, accS[k * 2 + 1]);
                    idx[k] = (idx[k] + F[k]) & 4095;
                }
            }
        } else if (uni) {
#pragma unroll
            for (int tt = 0; tt < 4; tt++) {
                ulonglong2 R0 = xs2[(0 * 4 + tt) * 32 + lane];
                ulonglong2 R8 = xs2[(1 * 4 + tt) * 32 + lane];
#pragma unroll
                for (int k = 0; k < 8; k++) {
                    ulonglong2 cs = ts2[idx[k]];
                    u64x prx = (k < 4) ? R0.x : R8.x;
                    u64x pry = (k < 4) ? R0.y : R8.y;
                    accR[k * 2 + 0] = fma2(prx, cs.x, accR[k * 2 + 0]);
                    accS[k * 2 + 0] = fma2(prx, cs.y, accS[k * 2 + 0]);
                    accR[k * 2 + 1] = fma2(pry, cs.x, accR[k * 2 + 1]);
                    accS[k * 2 + 1] = fma2(pry, cs.y, accS[k * 2 + 1]);
                    idx[k] = (idx[k] + F[k]) & 4095;
                }
            }
        } else {
            for (int tt = 0; tt < 4; tt++) {
#pragma unroll
                for (int k = 0; k < 8; k++) {
                    int j = F[k] & 15;
                    int jj = (j > 8) ? (16 - j) : j;
                    bool realu = (j == 0) || (j == 8);
                    int sR = (j == 0) ? 0 : ((j == 8) ? 1 : 2 * jj);
                    ulonglong2 RE = xs2[(sR * 4 + tt) * 32 + lane];
                    u64x pix = 0, piy = 0;
                    if (!realu) {
                        ulonglong2 IM = xs2[((2 * jj + 1) * 4 + tt) * 32 + lane];
                        pix = (j > 8) ? neg2(IM.x) : IM.x;
                        piy = (j > 8) ? neg2(IM.y) : IM.y;
                    }
                    ulonglong2 cs = ts2[idx[k]];
                    accR[k * 2 + 0] = fma2(RE.x, cs.x, accR[k * 2 + 0]);
                    accR[k * 2 + 0] = fma2(pix,  cs.y, accR[k * 2 + 0]);
                    accS[k * 2 + 0] = fma2(RE.x, cs.y, accS[k * 2 + 0]);
                    accS[k * 2 + 0] = fma2(neg2(pix), cs.x, accS[k * 2 + 0]);
                    accR[k * 2 + 1] = fma2(RE.y, cs.x, accR[k * 2 + 1]);
                    accR[k * 2 + 1] = fma2(piy,  cs.y, accR[k * 2 + 1]);
                    accS[k * 2 + 1] = fma2(RE.y, cs.y, accS[k * 2 + 1]);
                    accS[k * 2 + 1] = fma2(neg2(piy), cs.x, accS[k * 2 + 1]);
                    idx[k] = (idx[k] + F[k]) & 4095;
                }
            }
        }
    }

    const int ch = ctile * 128 + lane * 4;
    float2* dst = g_F + ((size_t)((tq * 2 + tensor) * NB + b) * NM) * NCH;
#pragma unroll
    for (int k = 0; k < 8; k++) {
        float r0, r1, r2, r3, s0, s1, s2, s3;
        unpack2(accR[k * 2 + 0], r0, r1);
        unpack2(accS[k * 2 + 0], s0, s1);
        unpack2(accR[k * 2 + 1], r2, r3);
        unpack2(accS[k * 2 + 1], s2, s3);
        float2* dp = &dst[(size_t)mi[k] * NCH + ch];
        *(float4*)(dp)     = make_float4(r0, -s0, r1, -s1);
        *(float4*)(dp + 2) = make_float4(r2, -s2, r3, -s3);
    }
}

// ================= K2a =================
#define K2A_SMEM (32 * 64 * 8 + 64 * 65 * 8 + 64 * 33 * 8)
__global__ void __launch_bounds__(256, 3) k2a_attn() {
    extern __shared__ char sm[];
    float2* sFq  = (float2*)sm;
    float2* sFkT = sFq + 32 * 64;
    float2* sA   = sFkT + 64 * 65;

    const int bh = blockIdx.x, b = bh >> 3, h = bh & 7;
    const int x0 = blockIdx.y * 32;
    const int tid = threadIdx.x;
    const size_t QSTR = (size_t)2 * NB * NM * NCH;

    for (int i = tid; i < 2048; i += 256) {
        int xl = i >> 6, e = i & 63;
        size_t o0 = ((size_t)(b) * NM + (x0 + xl)) * NCH + h * 64 + e;
        float2 a0 = g_F[o0], a1 = g_F[o0 + QSTR], a2 = g_F[o0 + 2 * QSTR], a3 = g_F[o0 + 3 * QSTR];
        sFq[xl * 64 + e] = make_float2(a0.x + a1.x + a2.x + a3.x, a0.y + a1.y + a2.y + a3.y);
    }
    for (int i = tid; i < 4096; i += 256) {
        int e = i & 63, f = i >> 6;
        size_t o0 = ((size_t)(NB + b) * NM + f) * NCH + h * 64 + e;
        float2 a0 = g_F[o0], a1 = g_F[o0 + QSTR], a2 = g_F[o0 + 2 * QSTR], a3 = g_F[o0 + 3 * QSTR];
        sFkT[e * 65 + f] = make_float2(a0.x + a1.x + a2.x + a3.x, a0.y + a1.y + a2.y + a3.y);
    }
    __syncthreads();

#pragma unroll 1
    for (int p = 0; p < 8; p++) {
        int i = p * 256 + tid, xl = i >> 6, y = i & 63;
        float re = 0.f, im = 0.f;
#pragma unroll 4
        for (int e = 0; e < 64; e++) {
            float2 a = sFq[xl * 64 + e];
            float2 c = sFkT[e * 65 + y];
            re += a.x * c.x - a.y * c.y;
            im += a.x * c.y + a.y * c.x;
        }
        sA[y * 33 + xl] = make_float2(tanhf(re), tanhf(im));
    }
    __syncthreads();

#pragma unroll 1
    for (int p = 0; p < 8; p++) {
        int i = p * 256 + tid, xl = i & 31, e = i >> 5;
        float re = 0.f, im = 0.f;
#pragma unroll 4
        for (int y = 0; y < 64; y++) {
            float2 a  = sA[y * 33 + xl];
            float2 kv = sFkT[e * 65 + y];
            re += a.x * kv.x - a.y * kv.y;
            im += a.x * kv.y + a.y * kv.x;
        }
        g_C[((size_t)(h * 8 + b) * 64 + e) * 64 + x0 + xl] = make_float2(re, im);
    }
}

// ================= K2b: weight contraction (R15 layout, deeper unroll) =================
#define K2B_SMEM (8 * 64 * 4 * 8)
__global__ void __launch_bounds__(256, 4) k2b_wproj(const float* __restrict__ w1,
                                                    const float* __restrict__ w2,
                                                    const int* __restrict__ iq) {
    extern __shared__ char sm[];
    float2* sC = (float2*)sm;

    const int h = blockIdx.x, x0 = blockIdx.y * 4;
    const int tid = threadIdx.x;

    for (int i = tid; i < 2048; i += 256) {
        int xl = i & 3, e = (i >> 2) & 63, b = i >> 8;
        sC[(b * 64 + e) * 4 + xl] = g_C[((size_t)(h * 8 + b) * 64 + e) * 64 + x0 + xl];
    }
    __syncthreads();

    const int xl = tid & 3, x = x0 + xl, o = tid >> 2;
    float accR[8], accI[8];
#pragma unroll
    for (int b = 0; b < 8; b++) { accR[b] = 0.f; accI[b] = 0.f; }

    size_t wbase = (((size_t)h * 64) * 64 + o) * 64 + x;
#pragma unroll 8
    for (int e = 0; e < 64; e++) {
        float wr = __ldg(w1 + wbase + (size_t)e * 4096);
        float wi = __ldg(w2 + wbase + (size_t)e * 4096);
#pragma unroll
        for (int b = 0; b < 8; b++) {
            float2 c = sC[(b * 64 + e) * 4 + xl];
            accR[b] += c.x * wr - c.y * wi;
            accI[b] += c.x * wi + c.y * wr;
        }
    }

    int fx = iq[x];
    float s = ((fx == 0) || (fx == NL / 2) ? 1.0f : 2.0f) * 9.313225746154785e-10f;
#pragma unroll
    for (int b = 0; b < 8; b++) {
        int row = (b * 8 + h) * 64 + o;
        g_O[(size_t)row * NM + x] = make_float2(s * accR[b], -s * accI[b]);
    }
}

// ================= K3: inverse sparse DFT (radix-8, conj-folded) =================
static __device__ __forceinline__ void k3_seg_real(int lo, int hi, const int2* __restrict__ sperm,
    const ulonglong2* __restrict__ sAd, const ulonglong2* __restrict__ sBd,
    const ulonglong2* __restrict__ ts2, int lane, int t0, u64x P[4])
{
#pragma unroll 2
    for (int pos = lo; pos < hi; pos++) {
        int2 pf = sperm[pos];
        ulonglong2 A = sAd[pf.x * 32 + lane], B = sBd[pf.x * 32 + lane];
        int id = (pf.y * t0) & 4095;
#pragma unroll
        for (int j = 0; j < 2; j++) {
            ulonglong2 cs = ts2[id];
            P[j * 2 + 0] = fma2(A.x, cs.x, P[j * 2 + 0]);  P[j * 2 + 0] = fma2(B.x, cs.y, P[j * 2 + 0]);
            P[j * 2 + 1] = fma2(A.y, cs.x, P[j * 2 + 1]);  P[j * 2 + 1] = fma2(B.y, cs.y, P[j * 2 + 1]);
            id = (id + pf.y) & 4095;
        }
    }
}
template<bool FOLD>
static __device__ __forceinline__ void k3_seg_cplx(int lo, int hi, const int2* __restrict__ sperm,
    const ulonglong2* __restrict__ sAd, const ulonglong2* __restrict__ sBd,
    const ulonglong2* __restrict__ ts2, int lane, int t0, u64x Vr[4], u64x Vi[4])
{
#pragma unroll 2
    for (int pos = lo; pos < hi; pos++) {
        int2 pf = sperm[pos];
        ulonglong2 A = sAd[pf.x * 32 + lane], B = sBd[pf.x * 32 + lane];
        u64x nAx = neg2(A.x), nAy = neg2(A.y);
        u64x nBx = neg2(B.x), nBy = neg2(B.y);
        int id = (pf.y * t0) & 4095;
#pragma unroll
        for (int j = 0; j < 2; j++) {
            ulonglong2 cs = ts2[id];
            Vr[j * 2 + 0] = fma2(A.x, cs.x, Vr[j * 2 + 0]);  Vr[j * 2 + 0] = fma2(B.x, cs.y, Vr[j * 2 + 0]);
            Vr[j * 2 + 1] = fma2(A.y, cs.x, Vr[j * 2 + 1]);  Vr[j * 2 + 1] = fma2(B.y, cs.y, Vr[j * 2 + 1]);
            if (!FOLD) {
                Vi[j * 2 + 0] = fma2(A.x, cs.y, Vi[j * 2 + 0]);  Vi[j * 2 + 0] = fma2(nBx, cs.x, Vi[j * 2 + 0]);
                Vi[j * 2 + 1] = fma2(A.y, cs.y, Vi[j * 2 + 1]);  Vi[j * 2 + 1] = fma2(nBy, cs.x, Vi[j * 2 + 1]);
            } else {
                Vi[j * 2 + 0] = fma2(B.x, cs.x, Vi[j * 2 + 0]);  Vi[j * 2 + 0] = fma2(nAx, cs.y, Vi[j * 2 + 0]);
                Vi[j * 2 + 1] = fma2(B.y, cs.x, Vi[j * 2 + 1]);  Vi[j * 2 + 1] = fma2(nAy, cs.y, Vi[j * 2 + 1]);
            }
            id = (id + pf.y) & 4095;
        }
    }
}

#define K3_SMEM (4096 * 16 + 32768 + 32768 + 128 * 33 * 4 + 64 * 8 + 64)
__global__ void __launch_bounds__(512, 1) k3_inverse(float* __restrict__ out,
                                                     const int* __restrict__ iq) {
    extern __shared__ char sm[];
    ulonglong2* ts2 = (ulonglong2*)sm;
    float* sA = (float*)(ts2 + 4096);
    float* sB = sA + 64 * 128;
    float* sT = sB + 64 * 128;                    // [128 rows][33]
    int2* sperm = (int2*)(sT + 128 * 33);
    int* soff = (int*)(sperm + 64);

    const int rt = blockIdx.x;
    const int tq = blockIdx.y;
    const int r0 = rt * 128;
    const int tid = threadIdx.x, lane = tid & 31, warp = tid >> 5;

    for (int i = tid; i < 4096; i += 512) ts2[i] = g_ts[i];
    for (int i = tid; i < 8192; i += 512) {
        int rr = i >> 6, f = i & 63;
        float2 v = g_O[(size_t)(r0 + rr) * NM + f];
        int half = rr >> 6, pr = (rr & 63) >> 1, sl = half * 2 + (rr & 1);
        sA[f * 128 + pr * 4 + sl] = v.x;
        sB[f * 128 + pr * 4 + sl] = v.y;
    }
    if (warp == 0) {
        const unsigned FULL = 0xffffffffu;
        int Flo = iq[lane], Fhi = iq[lane + 32];
        int clo = Flo & 7, chi = Fhi & 7;
        unsigned mlo[8], mhi[8];
        int off[9]; off[0] = 0;
#pragma unroll
        for (int c = 0; c < 8; c++) {
            mlo[c] = __ballot_sync(FULL, clo == c);
            mhi[c] = __ballot_sync(FULL, chi == c);
        }
#pragma unroll
        for (int c = 0; c < 8; c++) off[c + 1] = off[c] + __popc(mlo[c]) + __popc(mhi[c]);
        unsigned lmm = (1u << lane) - 1u;
        int p_lo = off[clo] + __popc(mlo[clo] & lmm);
        int p_hi = off[chi] + __popc(mlo[chi]) + __popc(mhi[chi] & lmm);
        sperm[p_lo] = make_int2(lane, Flo);
        sperm[p_hi] = make_int2(lane + 32, Fhi);
        if (lane < 9) soff[lane] = off[lane];
    }
    __syncthreads();

    const ulonglong2* sAd = (const ulonglong2*)sA;
    const ulonglong2* sBd = (const ulonglong2*)sB;
    int o[9];
#pragma unroll
    for (int c = 0; c < 9; c++) o[c] = soff[c];

#pragma unroll 1
    for (int pass = 0; pass < 4; pass++) {
        const int t0 = tq * 128 + pass * 32 + warp * 2;
        u64x P0[4], P4[4], V1r[4], V1i[4], V2r[4], V2i[4], V3r[4], V3i[4];
#pragma unroll
        for (int j = 0; j < 4; j++) {
            P0[j] = 0; P4[j] = 0; V1r[j] = 0; V1i[j] = 0;
            V2r[j] = 0; V2i[j] = 0; V3r[j] = 0; V3i[j] = 0;
        }

        k3_seg_real(o[0], o[1], sperm, sAd, sBd, ts2, lane, t0, P0);
        k3_seg_cplx<false>(o[1], o[2], sperm, sAd, sBd, ts2, lane, t0, V1r, V1i);
        k3_seg_cplx<false>(o[2], o[3], sperm, sAd, sBd, ts2, lane, t0, V2r, V2i);
        k3_seg_cplx<false>(o[3], o[4], sperm, sAd, sBd, ts2, lane, t0, V3r, V3i);
        k3_seg_real(o[4], o[5], sperm, sAd, sBd, ts2, lane, t0, P4);
        k3_seg_cplx<true>(o[5], o[6], sperm, sAd, sBd, ts2, lane, t0, V3r, V3i);
        k3_seg_cplx<true>(o[6], o[7], sperm, sAd, sBd, ts2, lane, t0, V2r, V2i);
        k3_seg_cplx<true>(o[7], o[8], sperm, sAd, sBd, ts2, lane, t0, V1r, V1i);

#pragma unroll 1
        for (int m = 0; m < 8; m++) {
            __syncthreads();
#pragma unroll
            for (int j = 0; j < 2; j++) {
#pragma unroll
                for (int p = 0; p < 2; p++) {
                    const int q = j * 2 + p;
                    u64x a = add2(P0[q], P4[q]);
                    u64x bb = sub2(P0[q], P4[q]);
                    u64x S;
                    if (m == 0) {
                        S = add2(add2(a, V1r[q]), add2(V2r[q], V3r[q]));
                    } else if (m == 1) {
                        u64x t1 = fma2(sub2(V1r[q], V1i[q]), KK2, bb);
                        u64x u2 = fma2(add2(V3r[q], V3i[q]), NKK2, neg2(V2i[q]));
                        S = add2(t1, u2);
                    } else if (m == 2) {
                        S = add2(sub2(sub2(a, V1i[q]), V2r[q]), V3i[q]);
                    } else if (m == 3) {
                        u64x t2 = fma2(add2(V1r[q], V1i[q]), NKK2, bb);
                        u64x u1 = fma2(sub2(V3r[q], V3i[q]), KK2, V2i[q]);
                        S = add2(t2, u1);
                    } else if (m == 4) {
                        S = sub2(add2(sub2(a, V1r[q]), V2r[q]), V3r[q]);
                    } else if (m == 5) {
                        u64x t1 = fma2(sub2(V1r[q], V1i[q]), NKK2, bb);
                        u64x u2 = fma2(add2(V3r[q], V3i[q]), KK2, neg2(V2i[q]));
                        S = add2(t1, u2);
                    } else if (m == 6) {
                        S = sub2(sub2(add2(a, V1i[q]), V2r[q]), V3i[q]);
                    } else {
                        u64x t2 = fma2(add2(V1r[q], V1i[q]), KK2, bb);
                        u64x u1 = fma2(sub2(V3r[q], V3i[q]), NKK2, V2i[q]);
                        S = add2(t2, u1);
                    }
                    float v0, v1;
                    unpack2(S, v0, v1);
                    int tl = warp * 2 + j;
                    int rbase = p * 64 + 2 * lane;
                    sT[rbase * 33 + tl]       = v0;
                    sT[(rbase + 1) * 33 + tl] = v1;
                }
            }
            __syncthreads();
            int tbase = m * 512 + tq * 128 + pass * 32;
#pragma unroll
            for (int ii = 0; ii < 2; ii++) {
                int i = ii * 512 + tid;
                int rr = i >> 3, c4 = i & 7;
                const float* sp = sT + rr * 33 + c4 * 4;
                float4 vv = make_float4(sp[0], sp[1], sp[2], sp[3]);
                *(float4*)&out[(size_t)(r0 + rr) * NL + tbase + c4 * 4] = vv;
            }
        }
    }
}

// ================= launch =================
extern "C" void kernel_launch(void* const* d_in, const int* in_sizes, int n_in,
                              void* d_out, int out_size) {
    const float* q  = (const float*)d_in[0];
    const float* k  = (const float*)d_in[1];
    const float* w1 = (const float*)d_in[3];
    const float* w2 = (const float*)d_in[4];
    const int* iq   = (const int*)d_in[5];
    const int* ikv  = (const int*)d_in[6];
    float* out = (float*)d_out;

    cudaFuncSetAttribute(k1_forward, cudaFuncAttributeMaxDynamicSharedMemorySize, K1_SMEM);
    cudaFuncSetAttribute(k2a_attn,   cudaFuncAttributeMaxDynamicSharedMemorySize, K2A_SMEM);
    cudaFuncSetAttribute(k2b_wproj,  cudaFuncAttributeMaxDynamicSharedMemorySize, K2B_SMEM);
    cudaFuncSetAttribute(k3_inverse, cudaFuncAttributeMaxDynamicSharedMemorySize, K3_SMEM);

    k0_init<<<16, 256>>>();
    k1_forward<<<dim3(4, NB, 8), 256, K1_SMEM>>>(q, k, iq, ikv);
    k2a_attn<<<dim3(NB * NH, 2), 256, K2A_SMEM>>>();
    k2b_wproj<<<dim3(NH, 16), 256, K2B_SMEM>>>(w1, w2, iq);
    k3_inverse<<<dim3(32, 4), 512, K3_SMEM>>>(out, iq);
}